// round 15
// baseline (speedup 1.0000x reference)
#include <cuda_runtime.h>
#include <math.h>

// ---------------- scratch ----------------------------------------------------
__device__ float g_h1[512 * 512];
__device__ float g_h2[512 * 512];
__device__ float g_h3[512 * 512];
__device__ float g_y [512 * 64];
__device__ float g_mean[64];
__device__ float g_deaths[512];       // sorted, padded with 1e30f
__device__ double g_acc[3];           // 0: target SSE, 1: homology, 2: compactness

// ---------------- 32x32-tile fp32 GEMM, 64 thr, 4x4/thread ------------------
// BIT-EXACTNESS CONTRACT (IDENTIFIED Round 9, candidate 12): each output
// element is ONE fused-FMA chain over k in strictly ascending order, then one
// fp32 bias add, then relu. Tiling/ownership may change; chain order may not.
// BM=BN=BK=32; double-buffered smem; float4 LDS; kk software pipeline.
template <bool RELU>
__global__ void __launch_bounds__(64, 4)
gemm44_kernel(const float* __restrict__ A,
              const float* __restrict__ Bm,
              const float* __restrict__ bias,
              float* __restrict__ C, int K, int N) {
    __shared__ __align__(16) float As[2][32][36];   // [buf][k][m], stride 36 (aligned float4)
    __shared__ __align__(16) float Bs[2][32][32];   // [buf][k][n]
    const int t  = threadIdx.x;            // 64 threads
    const int tx = t & 7, ty = t >> 3;     // 8 n-groups x 8 m-groups
    const int m0 = blockIdx.y * 32, n0 = blockIdx.x * 32;

    const int a_m  = t & 31;               // A row
    const int a_kh = (t >> 5) * 16;        // k half: 0 or 16
    const int b_k  = t & 31;               // B k-row
    const int b_ch = (t >> 5) * 16;        // col half: 0 or 16

    float4 av[4], bv[4];
#pragma unroll
    for (int i = 0; i < 4; i++) {
        av[i] = *reinterpret_cast<const float4*>(&A[(m0 + a_m) * K + a_kh + 4 * i]);
        bv[i] = *reinterpret_cast<const float4*>(&Bm[b_k * N + n0 + b_ch + 4 * i]);
    }
#pragma unroll
    for (int i = 0; i < 4; i++) {
        As[0][a_kh + 4 * i + 0][a_m] = av[i].x;
        As[0][a_kh + 4 * i + 1][a_m] = av[i].y;
        As[0][a_kh + 4 * i + 2][a_m] = av[i].z;
        As[0][a_kh + 4 * i + 3][a_m] = av[i].w;
        *reinterpret_cast<float4*>(&Bs[0][b_k][b_ch + 4 * i]) = bv[i];
    }
    __syncthreads();

    float c[4][4] = {};
    const int nk = K >> 5;
    for (int kt = 0; kt < nk; kt++) {
        const int cur = kt & 1;
        const bool more = (kt + 1) < nk;
        if (more) {
            const int k0 = (kt + 1) << 5;
#pragma unroll
            for (int i = 0; i < 4; i++) {
                av[i] = *reinterpret_cast<const float4*>(&A[(m0 + a_m) * K + k0 + a_kh + 4 * i]);
                bv[i] = *reinterpret_cast<const float4*>(&Bm[(k0 + b_k) * N + n0 + b_ch + 4 * i]);
            }
        }
        float4 af = *reinterpret_cast<const float4*>(&As[cur][0][ty * 4]);
        float4 bf = *reinterpret_cast<const float4*>(&Bs[cur][0][tx * 4]);
#pragma unroll
        for (int kk = 0; kk < 32; kk++) {
            float4 an, bn;
            if (kk < 31) {
                an = *reinterpret_cast<const float4*>(&As[cur][kk + 1][ty * 4]);
                bn = *reinterpret_cast<const float4*>(&Bs[cur][kk + 1][tx * 4]);
            }
            c[0][0] = fmaf(af.x, bf.x, c[0][0]);
            c[0][1] = fmaf(af.x, bf.y, c[0][1]);
            c[0][2] = fmaf(af.x, bf.z, c[0][2]);
            c[0][3] = fmaf(af.x, bf.w, c[0][3]);
            c[1][0] = fmaf(af.y, bf.x, c[1][0]);
            c[1][1] = fmaf(af.y, bf.y, c[1][1]);
            c[1][2] = fmaf(af.y, bf.z, c[1][2]);
            c[1][3] = fmaf(af.y, bf.w, c[1][3]);
            c[2][0] = fmaf(af.z, bf.x, c[2][0]);
            c[2][1] = fmaf(af.z, bf.y, c[2][1]);
            c[2][2] = fmaf(af.z, bf.z, c[2][2]);
            c[2][3] = fmaf(af.z, bf.w, c[2][3]);
            c[3][0] = fmaf(af.w, bf.x, c[3][0]);
            c[3][1] = fmaf(af.w, bf.y, c[3][1]);
            c[3][2] = fmaf(af.w, bf.z, c[3][2]);
            c[3][3] = fmaf(af.w, bf.w, c[3][3]);
            if (kk < 31) { af = an; bf = bn; }
        }
        if (more) {
            const int nxt = cur ^ 1;
#pragma unroll
            for (int i = 0; i < 4; i++) {
                As[nxt][a_kh + 4 * i + 0][a_m] = av[i].x;
                As[nxt][a_kh + 4 * i + 1][a_m] = av[i].y;
                As[nxt][a_kh + 4 * i + 2][a_m] = av[i].z;
                As[nxt][a_kh + 4 * i + 3][a_m] = av[i].w;
                *reinterpret_cast<float4*>(&Bs[nxt][b_k][b_ch + 4 * i]) = bv[i];
            }
            __syncthreads();
        }
    }
    const float4 bb = *reinterpret_cast<const float4*>(&bias[n0 + tx * 4]);
#pragma unroll
    for (int i = 0; i < 4; i++) {
        int m = m0 + ty * 4 + i;
        float4 v;
        v.x = __fadd_rn(c[i][0], bb.x);
        v.y = __fadd_rn(c[i][1], bb.y);
        v.z = __fadd_rn(c[i][2], bb.z);
        v.w = __fadd_rn(c[i][3], bb.w);
        if (RELU) {
            v.x = fmaxf(v.x, 0.0f); v.y = fmaxf(v.y, 0.0f);
            v.z = fmaxf(v.z, 0.0f); v.w = fmaxf(v.w, 0.0f);
        }
        *reinterpret_cast<float4*>(&C[m * N + n0 + tx * 4]) = v;
    }
}

// ---------------- final layer: y = h3 @ Wout + bout  (512x512 @ 512x64) ----
// Same contract: single sequential ascending-k FFMA chain per element.
__global__ void gemm_out_kernel(const float* __restrict__ A,
                                const float* __restrict__ W,
                                const float* __restrict__ bias,
                                float* __restrict__ Y) {
    __shared__ float a[4][512];
    const int r0 = blockIdx.x * 4;
    const int t  = threadIdx.x;  // 64
    for (int idx = t; idx < 4 * 512; idx += 64)
        a[idx >> 9][idx & 511] = A[(r0 + (idx >> 9)) * 512 + (idx & 511)];
    __syncthreads();
    float acc[4] = {};
#pragma unroll 16
    for (int k = 0; k < 512; k++) {
        float w = W[k * 64 + t];         // coalesced; Wout stays in L2
#pragma unroll
        for (int r = 0; r < 4; r++) acc[r] = fmaf(a[r][k], w, acc[r]);
    }
    float b = bias[t];
#pragma unroll
    for (int r = 0; r < 4; r++) Y[(r0 + r) * 64 + t] = __fadd_rn(acc[r], b);
}

// ---------------- column means of y (4-partial fixed-order tree) ------------
__global__ void col_mean_kernel(const float* __restrict__ y) {
    __shared__ float ps[4][64];
    const int t = threadIdx.x;    // 256
    const int c = t & 63, p = t >> 6;
    float s = 0.0f;
    for (int r = p * 128; r < (p + 1) * 128; r++) s += y[r * 64 + c];
    ps[p][c] = s;
    __syncthreads();
    if (t < 64) {
        float v = __fadd_rn(__fadd_rn(__fadd_rn(ps[0][t], ps[1][t]), ps[2][t]), ps[3][t]);
        g_mean[t] = v * (1.0f / 512.0f);
    }
}

// ---------------- target MSE (as SSE) + compactness sum --------------------
__global__ void reduce_tc_kernel(const float* __restrict__ y,
                                 const float* __restrict__ target) {
    __shared__ double st[256];
    __shared__ double sc[256];
    const int tid = threadIdx.x;
    double t_sum = 0.0, c_sum = 0.0;
    for (int idx = blockIdx.x * 256 + tid; idx < 512 * 64; idx += gridDim.x * 256) {
        float yv = y[idx];
        float d  = target[idx] - yv;
        t_sum += (double)d * (double)d;
        c_sum += fabs((double)(yv - g_mean[idx & 63]));
    }
    st[tid] = t_sum; sc[tid] = c_sum;
    __syncthreads();
    for (int s = 128; s > 0; s >>= 1) {
        if (tid < s) { st[tid] += st[tid + s]; sc[tid] += sc[tid + s]; }
        __syncthreads();
    }
    if (tid == 0) {
        atomicAdd(&g_acc[0], st[0]);
        atomicAdd(&g_acc[2], sc[0]);
    }
}

// ---------------- sort deaths + reset accumulators --------------------------
__global__ void sort_deaths_kernel(const float* __restrict__ d, int n) {
    __shared__ float s[512];
    const int t = threadIdx.x;  // 512
    if (t < 3) g_acc[t] = 0.0;  // graph replays must be idempotent
    s[t] = (t < n) ? d[t] : 1e30f;
    __syncthreads();
    for (int k = 2; k <= 512; k <<= 1) {
        for (int j = k >> 1; j > 0; j >>= 1) {
            int ixj = t ^ j;
            if (ixj > t) {
                bool up = ((t & k) == 0);
                float a = s[t], b = s[ixj];
                if ((a > b) == up) { s[t] = b; s[ixj] = a; }
            }
            __syncthreads();
        }
    }
    g_deaths[t] = s[t];
}

// ---------------- pdist + tolerance match + homology sum --------------------
// BIT-EXACTNESS CONTRACT (IDENTIFIED Round 9, order 12):
//   16 leaves, leaf_q sequential: ((d_q^2 + d_{q+16}^2) + d_{q+32}^2) + d_{q+48}^2
//   then stride tree offsets 8,4,2,1 (fl adds), pd = fp32 sqrt.
// All via __fadd_rn/__fmul_rn so ptxas cannot contract to FMA.
// isclose in fp32 exactly as jax: |a-b| <= 1e-8f + 1e-6f*|b|.
__device__ __forceinline__ double pdist_row(const float* __restrict__ yi,
                                            const float* __restrict__ y,
                                            const float* __restrict__ ds,
                                            int i, int t, int n_deaths) {
    double local = 0.0;
    const float4* a4 = reinterpret_cast<const float4*>(yi);
    for (int j = i + 1 + t; j < 512; j += 128) {
        const float4* b4 = reinterpret_cast<const float4*>(y + j * 64);
        float d[64];
#pragma unroll
        for (int k = 0; k < 16; k++) {
            float4 a = a4[k], b = b4[k];
            d[4 * k]     = __fadd_rn(a.x, -b.x);
            d[4 * k + 1] = __fadd_rn(a.y, -b.y);
            d[4 * k + 2] = __fadd_rn(a.z, -b.z);
            d[4 * k + 3] = __fadd_rn(a.w, -b.w);
        }
        float l[16];
#pragma unroll
        for (int q = 0; q < 16; q++) {
            float s0 = __fmul_rn(d[q], d[q]);
            s0 = __fadd_rn(s0, __fmul_rn(d[q + 16], d[q + 16]));
            s0 = __fadd_rn(s0, __fmul_rn(d[q + 32], d[q + 32]));
            l[q] = __fadd_rn(s0, __fmul_rn(d[q + 48], d[q + 48]));
        }
#pragma unroll
        for (int off = 8; off > 0; off >>= 1)
#pragma unroll
            for (int q = 0; q < 8; q++)
                if (q < off) l[q] = __fadd_rn(l[q], l[q + off]);
        float pd = __fsqrt_rn(l[0]);

        int lo = 0, hi = 512;
        while (lo < hi) {
            int mid = (lo + hi) >> 1;
            if (ds[mid] < pd) lo = mid + 1; else hi = mid;
        }
        bool matched = false;
        int q0 = lo - 3 < 0 ? 0 : lo - 3;
        int q1 = lo + 2 < n_deaths - 1 ? lo + 2 : n_deaths - 1;
        for (int q = q0; q <= q1; q++) {
            float dd = ds[q];
            float rhs = __fadd_rn(1e-8f, __fmul_rn(1e-6f, fabsf(dd)));
            if (fabsf(__fadd_rn(pd, -dd)) <= rhs) matched = true;
        }
        if (matched) local += (double)pd;  // birth=0, EPS=0, pd>0
    }
    return local;
}

// Balanced: block b handles rows {b, 510-b} -> 512 pairs per block (const).
__global__ void pdist_hom_kernel(const float* __restrict__ y, int n_deaths) {
    __shared__ __align__(16) float yi[2][64];
    __shared__ float ds[512];
    __shared__ double red[128];
    const int b = blockIdx.x;   // 256 blocks
    const int t = threadIdx.x;  // 128
    const int i1 = b, i2 = 510 - b;
    if (t < 64) yi[0][t] = y[i1 * 64 + t];
    else if (i2 > i1) yi[1][t - 64] = y[i2 * 64 + (t - 64)];
    for (int k = t; k < 512; k += 128) ds[k] = g_deaths[k];
    __syncthreads();

    double local = pdist_row(yi[0], y, ds, i1, t, n_deaths);
    if (i2 > i1) local += pdist_row(yi[1], y, ds, i2, t, n_deaths);

    red[t] = local;
    __syncthreads();
    for (int s2 = 64; s2 > 0; s2 >>= 1) {
        if (t < s2) red[t] += red[t + s2];
        __syncthreads();
    }
    if (t == 0) atomicAdd(&g_acc[1], red[0]);
}

// ---------------- finalize ---------------------------------------------------
__global__ void finalize_kernel(float* __restrict__ out) {
    out[0] = (float)(g_acc[0] * (1.0 / 32768.0) + g_acc[1] + 0.01 * g_acc[2]);
}

// ---------------- launch -----------------------------------------------------
extern "C" void kernel_launch(void* const* d_in, const int* in_sizes, int n_in,
                              void* d_out, int out_size) {
    const float* batch  = (const float*)d_in[0];   // [512,256]
    const float* target = (const float*)d_in[1];   // [512,64]
    const float* W1     = (const float*)d_in[2];   // [256,512]
    const float* b1     = (const float*)d_in[3];
    const float* W2     = (const float*)d_in[4];   // [512,512]
    const float* b2     = (const float*)d_in[5];
    const float* W3     = (const float*)d_in[6];   // [512,512]
    const float* b3     = (const float*)d_in[7];
    const float* Wout   = (const float*)d_in[8];   // [512,64]
    const float* bout   = (const float*)d_in[9];
    const float* deaths = (const float*)d_in[10];  // [511]
    const int n_deaths  = in_sizes[10];
    float* out = (float*)d_out;

    void *p1, *p2, *p3, *py;
    cudaGetSymbolAddress(&p1, g_h1);
    cudaGetSymbolAddress(&p2, g_h2);
    cudaGetSymbolAddress(&p3, g_h3);
    cudaGetSymbolAddress(&py, g_y);
    float* h1 = (float*)p1; float* h2 = (float*)p2;
    float* h3 = (float*)p3; float* y  = (float*)py;

    sort_deaths_kernel<<<1, 512>>>(deaths, n_deaths);
    gemm44_kernel<true><<<dim3(16, 16), 64>>>(batch, W1, b1, h1, 256, 512);
    gemm44_kernel<true><<<dim3(16, 16), 64>>>(h1,    W2, b2, h2, 512, 512);
    gemm44_kernel<true><<<dim3(16, 16), 64>>>(h2,    W3, b3, h3, 512, 512);
    gemm_out_kernel<<<128, 64>>>(h3, Wout, bout, y);
    col_mean_kernel<<<1, 256>>>(y);
    reduce_tc_kernel<<<64, 256>>>(y, target);
    pdist_hom_kernel<<<256, 128>>>(y, n_deaths);
    finalize_kernel<<<1, 1>>>(out);
}

// round 16
// speedup vs baseline: 1.0023x; 1.0023x over previous
#include <cuda_runtime.h>
#include <math.h>

// ---------------- scratch ----------------------------------------------------
__device__ float g_h1[512 * 512];
__device__ float g_h2[512 * 512];
__device__ float g_h3[512 * 512];
__device__ float g_y [512 * 64];
__device__ float g_mean[64];
__device__ float g_deaths[512];       // sorted, padded with 1e30f
__device__ double g_acc[3];           // 0: target SSE, 1: homology, 2: compactness

// ---------------- 32x32-tile fp32 GEMM, 64 thr, 4x4/thread ------------------
// BIT-EXACTNESS CONTRACT (IDENTIFIED Round 9, candidate 12): each output
// element is ONE fused-FMA chain over k in strictly ascending order, then one
// fp32 bias add, then relu. Tiling/ownership may change; chain order may not.
// BM=BN=BK=32; double-buffered smem; float4 LDS; kk software pipeline.
template <bool RELU>
__global__ void __launch_bounds__(64, 4)
gemm44_kernel(const float* __restrict__ A,
              const float* __restrict__ Bm,
              const float* __restrict__ bias,
              float* __restrict__ C, int K, int N) {
    __shared__ __align__(16) float As[2][32][36];   // [buf][k][m], stride 36 (aligned float4)
    __shared__ __align__(16) float Bs[2][32][32];   // [buf][k][n]
    const int t  = threadIdx.x;            // 64 threads
    const int tx = t & 7, ty = t >> 3;     // 8 n-groups x 8 m-groups
    const int m0 = blockIdx.y * 32, n0 = blockIdx.x * 32;

    const int a_m  = t & 31;               // A row
    const int a_kh = (t >> 5) * 16;        // k half: 0 or 16
    const int b_k  = t & 31;               // B k-row
    const int b_ch = (t >> 5) * 16;        // col half: 0 or 16

    float4 av[4], bv[4];
#pragma unroll
    for (int i = 0; i < 4; i++) {
        av[i] = *reinterpret_cast<const float4*>(&A[(m0 + a_m) * K + a_kh + 4 * i]);
        bv[i] = *reinterpret_cast<const float4*>(&Bm[b_k * N + n0 + b_ch + 4 * i]);
    }
#pragma unroll
    for (int i = 0; i < 4; i++) {
        As[0][a_kh + 4 * i + 0][a_m] = av[i].x;
        As[0][a_kh + 4 * i + 1][a_m] = av[i].y;
        As[0][a_kh + 4 * i + 2][a_m] = av[i].z;
        As[0][a_kh + 4 * i + 3][a_m] = av[i].w;
        *reinterpret_cast<float4*>(&Bs[0][b_k][b_ch + 4 * i]) = bv[i];
    }
    __syncthreads();

    float c[4][4] = {};
    const int nk = K >> 5;
    for (int kt = 0; kt < nk; kt++) {
        const int cur = kt & 1;
        const bool more = (kt + 1) < nk;
        if (more) {
            const int k0 = (kt + 1) << 5;
#pragma unroll
            for (int i = 0; i < 4; i++) {
                av[i] = *reinterpret_cast<const float4*>(&A[(m0 + a_m) * K + k0 + a_kh + 4 * i]);
                bv[i] = *reinterpret_cast<const float4*>(&Bm[(k0 + b_k) * N + n0 + b_ch + 4 * i]);
            }
        }
        float4 af = *reinterpret_cast<const float4*>(&As[cur][0][ty * 4]);
        float4 bf = *reinterpret_cast<const float4*>(&Bs[cur][0][tx * 4]);
#pragma unroll
        for (int kk = 0; kk < 32; kk++) {
            float4 an, bn;
            if (kk < 31) {
                an = *reinterpret_cast<const float4*>(&As[cur][kk + 1][ty * 4]);
                bn = *reinterpret_cast<const float4*>(&Bs[cur][kk + 1][tx * 4]);
            }
            c[0][0] = fmaf(af.x, bf.x, c[0][0]);
            c[0][1] = fmaf(af.x, bf.y, c[0][1]);
            c[0][2] = fmaf(af.x, bf.z, c[0][2]);
            c[0][3] = fmaf(af.x, bf.w, c[0][3]);
            c[1][0] = fmaf(af.y, bf.x, c[1][0]);
            c[1][1] = fmaf(af.y, bf.y, c[1][1]);
            c[1][2] = fmaf(af.y, bf.z, c[1][2]);
            c[1][3] = fmaf(af.y, bf.w, c[1][3]);
            c[2][0] = fmaf(af.z, bf.x, c[2][0]);
            c[2][1] = fmaf(af.z, bf.y, c[2][1]);
            c[2][2] = fmaf(af.z, bf.z, c[2][2]);
            c[2][3] = fmaf(af.z, bf.w, c[2][3]);
            c[3][0] = fmaf(af.w, bf.x, c[3][0]);
            c[3][1] = fmaf(af.w, bf.y, c[3][1]);
            c[3][2] = fmaf(af.w, bf.z, c[3][2]);
            c[3][3] = fmaf(af.w, bf.w, c[3][3]);
            if (kk < 31) { af = an; bf = bn; }
        }
        if (more) {
            const int nxt = cur ^ 1;
#pragma unroll
            for (int i = 0; i < 4; i++) {
                As[nxt][a_kh + 4 * i + 0][a_m] = av[i].x;
                As[nxt][a_kh + 4 * i + 1][a_m] = av[i].y;
                As[nxt][a_kh + 4 * i + 2][a_m] = av[i].z;
                As[nxt][a_kh + 4 * i + 3][a_m] = av[i].w;
                *reinterpret_cast<float4*>(&Bs[nxt][b_k][b_ch + 4 * i]) = bv[i];
            }
            __syncthreads();
        }
    }
    const float4 bb = *reinterpret_cast<const float4*>(&bias[n0 + tx * 4]);
#pragma unroll
    for (int i = 0; i < 4; i++) {
        int m = m0 + ty * 4 + i;
        float4 v;
        v.x = __fadd_rn(c[i][0], bb.x);
        v.y = __fadd_rn(c[i][1], bb.y);
        v.z = __fadd_rn(c[i][2], bb.z);
        v.w = __fadd_rn(c[i][3], bb.w);
        if (RELU) {
            v.x = fmaxf(v.x, 0.0f); v.y = fmaxf(v.y, 0.0f);
            v.z = fmaxf(v.z, 0.0f); v.w = fmaxf(v.w, 0.0f);
        }
        *reinterpret_cast<float4*>(&C[m * N + n0 + tx * 4]) = v;
    }
}

// ---------------- final layer: y = h3 @ Wout + bout  (512x512 @ 512x64) ----
// Same contract: single sequential ascending-k FFMA chain per element.
__global__ void gemm_out_kernel(const float* __restrict__ A,
                                const float* __restrict__ W,
                                const float* __restrict__ bias,
                                float* __restrict__ Y) {
    __shared__ float a[4][512];
    const int r0 = blockIdx.x * 4;
    const int t  = threadIdx.x;  // 64
    for (int idx = t; idx < 4 * 512; idx += 64)
        a[idx >> 9][idx & 511] = A[(r0 + (idx >> 9)) * 512 + (idx & 511)];
    __syncthreads();
    float acc[4] = {};
#pragma unroll 16
    for (int k = 0; k < 512; k++) {
        float w = W[k * 64 + t];         // coalesced; Wout stays in L2
#pragma unroll
        for (int r = 0; r < 4; r++) acc[r] = fmaf(a[r][k], w, acc[r]);
    }
    float b = bias[t];
#pragma unroll
    for (int r = 0; r < 4; r++) Y[(r0 + r) * 64 + t] = __fadd_rn(acc[r], b);
}

// ---------------- column means of y (4-partial fixed-order tree) ------------
__global__ void col_mean_kernel(const float* __restrict__ y) {
    __shared__ float ps[4][64];
    const int t = threadIdx.x;    // 256
    const int c = t & 63, p = t >> 6;
    float s = 0.0f;
    for (int r = p * 128; r < (p + 1) * 128; r++) s += y[r * 64 + c];
    ps[p][c] = s;
    __syncthreads();
    if (t < 64) {
        float v = __fadd_rn(__fadd_rn(__fadd_rn(ps[0][t], ps[1][t]), ps[2][t]), ps[3][t]);
        g_mean[t] = v * (1.0f / 512.0f);
    }
}

// ---------------- target MSE (as SSE) + compactness sum --------------------
__global__ void reduce_tc_kernel(const float* __restrict__ y,
                                 const float* __restrict__ target) {
    __shared__ double st[256];
    __shared__ double sc[256];
    const int tid = threadIdx.x;
    double t_sum = 0.0, c_sum = 0.0;
    for (int idx = blockIdx.x * 256 + tid; idx < 512 * 64; idx += gridDim.x * 256) {
        float yv = y[idx];
        float d  = target[idx] - yv;
        t_sum += (double)d * (double)d;
        c_sum += fabs((double)(yv - g_mean[idx & 63]));
    }
    st[tid] = t_sum; sc[tid] = c_sum;
    __syncthreads();
    for (int s = 128; s > 0; s >>= 1) {
        if (tid < s) { st[tid] += st[tid + s]; sc[tid] += sc[tid + s]; }
        __syncthreads();
    }
    if (tid == 0) {
        atomicAdd(&g_acc[0], st[0]);
        atomicAdd(&g_acc[2], sc[0]);
    }
}

// ---------------- sort deaths + reset accumulators --------------------------
__global__ void sort_deaths_kernel(const float* __restrict__ d, int n) {
    __shared__ float s[512];
    const int t = threadIdx.x;  // 512
    if (t < 3) g_acc[t] = 0.0;  // graph replays must be idempotent
    s[t] = (t < n) ? d[t] : 1e30f;
    __syncthreads();
    for (int k = 2; k <= 512; k <<= 1) {
        for (int j = k >> 1; j > 0; j >>= 1) {
            int ixj = t ^ j;
            if (ixj > t) {
                bool up = ((t & k) == 0);
                float a = s[t], b = s[ixj];
                if ((a > b) == up) { s[t] = b; s[ixj] = a; }
            }
            __syncthreads();
        }
    }
    g_deaths[t] = s[t];
}

// ---------------- pdist + tolerance match + homology sum --------------------
// BIT-EXACTNESS CONTRACT (IDENTIFIED Round 9, order 12):
//   16 leaves, leaf_q sequential: ((d_q^2 + d_{q+16}^2) + d_{q+32}^2) + d_{q+48}^2
//   then stride tree offsets 8,4,2,1 (fl adds), pd = fp32 sqrt.
// All via __fadd_rn/__fmul_rn so ptxas cannot contract to FMA.
// isclose in fp32 exactly as jax: |a-b| <= 1e-8f + 1e-6f*|b|.
__device__ __forceinline__ double pdist_row(const float* __restrict__ yi,
                                            const float* __restrict__ y,
                                            const float* __restrict__ ds,
                                            int i, int t, int n_deaths) {
    double local = 0.0;
    const float4* a4 = reinterpret_cast<const float4*>(yi);
    for (int j = i + 1 + t; j < 512; j += 128) {
        const float4* b4 = reinterpret_cast<const float4*>(y + j * 64);
        float d[64];
#pragma unroll
        for (int k = 0; k < 16; k++) {
            float4 a = a4[k], b = b4[k];
            d[4 * k]     = __fadd_rn(a.x, -b.x);
            d[4 * k + 1] = __fadd_rn(a.y, -b.y);
            d[4 * k + 2] = __fadd_rn(a.z, -b.z);
            d[4 * k + 3] = __fadd_rn(a.w, -b.w);
        }
        float l[16];
#pragma unroll
        for (int q = 0; q < 16; q++) {
            float s0 = __fmul_rn(d[q], d[q]);
            s0 = __fadd_rn(s0, __fmul_rn(d[q + 16], d[q + 16]));
            s0 = __fadd_rn(s0, __fmul_rn(d[q + 32], d[q + 32]));
            l[q] = __fadd_rn(s0, __fmul_rn(d[q + 48], d[q + 48]));
        }
#pragma unroll
        for (int off = 8; off > 0; off >>= 1)
#pragma unroll
            for (int q = 0; q < 8; q++)
                if (q < off) l[q] = __fadd_rn(l[q], l[q + off]);
        float pd = __fsqrt_rn(l[0]);

        int lo = 0, hi = 512;
        while (lo < hi) {
            int mid = (lo + hi) >> 1;
            if (ds[mid] < pd) lo = mid + 1; else hi = mid;
        }
        bool matched = false;
        int q0 = lo - 3 < 0 ? 0 : lo - 3;
        int q1 = lo + 2 < n_deaths - 1 ? lo + 2 : n_deaths - 1;
        for (int q = q0; q <= q1; q++) {
            float dd = ds[q];
            float rhs = __fadd_rn(1e-8f, __fmul_rn(1e-6f, fabsf(dd)));
            if (fabsf(__fadd_rn(pd, -dd)) <= rhs) matched = true;
        }
        if (matched) local += (double)pd;  // birth=0, EPS=0, pd>0
    }
    return local;
}

// Balanced: block b handles rows {b, 510-b} -> 512 pairs per block (const).
__global__ void pdist_hom_kernel(const float* __restrict__ y, int n_deaths) {
    __shared__ __align__(16) float yi[2][64];
    __shared__ float ds[512];
    __shared__ double red[128];
    const int b = blockIdx.x;   // 256 blocks
    const int t = threadIdx.x;  // 128
    const int i1 = b, i2 = 510 - b;
    if (t < 64) yi[0][t] = y[i1 * 64 + t];
    else if (i2 > i1) yi[1][t - 64] = y[i2 * 64 + (t - 64)];
    for (int k = t; k < 512; k += 128) ds[k] = g_deaths[k];
    __syncthreads();

    double local = pdist_row(yi[0], y, ds, i1, t, n_deaths);
    if (i2 > i1) local += pdist_row(yi[1], y, ds, i2, t, n_deaths);

    red[t] = local;
    __syncthreads();
    for (int s2 = 64; s2 > 0; s2 >>= 1) {
        if (t < s2) red[t] += red[t + s2];
        __syncthreads();
    }
    if (t == 0) atomicAdd(&g_acc[1], red[0]);
}

// ---------------- finalize ---------------------------------------------------
__global__ void finalize_kernel(float* __restrict__ out) {
    out[0] = (float)(g_acc[0] * (1.0 / 32768.0) + g_acc[1] + 0.01 * g_acc[2]);
}

// ---------------- launch -----------------------------------------------------
extern "C" void kernel_launch(void* const* d_in, const int* in_sizes, int n_in,
                              void* d_out, int out_size) {
    const float* batch  = (const float*)d_in[0];   // [512,256]
    const float* target = (const float*)d_in[1];   // [512,64]
    const float* W1     = (const float*)d_in[2];   // [256,512]
    const float* b1     = (const float*)d_in[3];
    const float* W2     = (const float*)d_in[4];   // [512,512]
    const float* b2     = (const float*)d_in[5];
    const float* W3     = (const float*)d_in[6];   // [512,512]
    const float* b3     = (const float*)d_in[7];
    const float* Wout   = (const float*)d_in[8];   // [512,64]
    const float* bout   = (const float*)d_in[9];
    const float* deaths = (const float*)d_in[10];  // [511]
    const int n_deaths  = in_sizes[10];
    float* out = (float*)d_out;

    void *p1, *p2, *p3, *py;
    cudaGetSymbolAddress(&p1, g_h1);
    cudaGetSymbolAddress(&p2, g_h2);
    cudaGetSymbolAddress(&p3, g_h3);
    cudaGetSymbolAddress(&py, g_y);
    float* h1 = (float*)p1; float* h2 = (float*)p2;
    float* h3 = (float*)p3; float* y  = (float*)py;

    sort_deaths_kernel<<<1, 512>>>(deaths, n_deaths);
    gemm44_kernel<true><<<dim3(16, 16), 64>>>(batch, W1, b1, h1, 256, 512);
    gemm44_kernel<true><<<dim3(16, 16), 64>>>(h1,    W2, b2, h2, 512, 512);
    gemm44_kernel<true><<<dim3(16, 16), 64>>>(h2,    W3, b3, h3, 512, 512);
    gemm_out_kernel<<<128, 64>>>(h3, Wout, bout, y);
    col_mean_kernel<<<1, 256>>>(y);
    reduce_tc_kernel<<<64, 256>>>(y, target);
    pdist_hom_kernel<<<256, 128>>>(y, n_deaths);
    finalize_kernel<<<1, 1>>>(out);
}

// round 17
// speedup vs baseline: 1.1777x; 1.1750x over previous
#include <cuda_runtime.h>
#include <math.h>

// ---------------- scratch ----------------------------------------------------
__device__ float g_h1[512 * 512];
__device__ float g_h2[512 * 512];
__device__ float g_h3[512 * 512];
__device__ float g_y [512 * 64];
__device__ float g_mean[64];
__device__ float g_deaths[512];       // sorted, padded with 1e30f
__device__ double g_acc[3];           // 0: target SSE, 1: homology, 2: compactness

// ---------------- 32x32-tile fp32 GEMM (R13 measured-best config) -----------
// BIT-EXACTNESS CONTRACT (IDENTIFIED Round 9, candidate 12): each output
// element is ONE fused-FMA chain over k in strictly ascending order, then one
// fp32 bias add, then relu. Tiling/ownership may change; chain order may not.
// 128 threads (4 warps), BM=BN=BK=32, 2x4/thread, double-buffered smem,
// vector LDS with kk software pipeline. Grid 256 -> ~2 CTAs/SM.
template <bool RELU>
__global__ void __launch_bounds__(128, 2)
gemm32_kernel(const float* __restrict__ A,
              const float* __restrict__ Bm,
              const float* __restrict__ bias,
              float* __restrict__ C, int K, int N) {
    __shared__ __align__(16) float As[2][32][34];   // [buf][k][m]
    __shared__ __align__(16) float Bs[2][32][32];   // [buf][k][n]
    const int t  = threadIdx.x;            // 128 threads
    const int tx = t & 7, ty = t >> 3;     // 8 n-groups x 16 m-groups
    const int m0 = blockIdx.y * 32, n0 = blockIdx.x * 32;

    const int a_m  = t >> 2;               // 32 rows
    const int a_k4 = (t & 3) * 4;          // k offsets {0,4,8,12}, +16 second
    const int b_k  = t >> 2;               // 32 k-rows
    const int b_c4 = (t & 3) * 4;          // col offsets {0,4,8,12}, +16 second

    // prologue: k-tile 0 into buf 0
    float4 a0 = *reinterpret_cast<const float4*>(&A[(m0 + a_m) * K + a_k4]);
    float4 a1 = *reinterpret_cast<const float4*>(&A[(m0 + a_m) * K + a_k4 + 16]);
    float4 bb0 = *reinterpret_cast<const float4*>(&Bm[b_k * N + n0 + b_c4]);
    float4 bb1 = *reinterpret_cast<const float4*>(&Bm[b_k * N + n0 + b_c4 + 16]);
    As[0][a_k4    ][a_m] = a0.x; As[0][a_k4 + 1][a_m] = a0.y;
    As[0][a_k4 + 2][a_m] = a0.z; As[0][a_k4 + 3][a_m] = a0.w;
    As[0][a_k4 + 16][a_m] = a1.x; As[0][a_k4 + 17][a_m] = a1.y;
    As[0][a_k4 + 18][a_m] = a1.z; As[0][a_k4 + 19][a_m] = a1.w;
    *reinterpret_cast<float4*>(&Bs[0][b_k][b_c4])      = bb0;
    *reinterpret_cast<float4*>(&Bs[0][b_k][b_c4 + 16]) = bb1;
    __syncthreads();

    float c[2][4] = {};
    const int nk = K >> 5;
    for (int kt = 0; kt < nk; kt++) {
        const int cur = kt & 1;
        const bool more = (kt + 1) < nk;
        if (more) {
            const int k0 = (kt + 1) << 5;
            a0  = *reinterpret_cast<const float4*>(&A[(m0 + a_m) * K + k0 + a_k4]);
            a1  = *reinterpret_cast<const float4*>(&A[(m0 + a_m) * K + k0 + a_k4 + 16]);
            bb0 = *reinterpret_cast<const float4*>(&Bm[(k0 + b_k) * N + n0 + b_c4]);
            bb1 = *reinterpret_cast<const float4*>(&Bm[(k0 + b_k) * N + n0 + b_c4 + 16]);
        }
        // software-pipelined inner loop
        float2 ac = *reinterpret_cast<const float2*>(&As[cur][0][ty * 2]);
        float4 bc = *reinterpret_cast<const float4*>(&Bs[cur][0][tx * 4]);
#pragma unroll
        for (int kk = 0; kk < 32; kk++) {
            float2 an; float4 bn;
            if (kk < 31) {
                an = *reinterpret_cast<const float2*>(&As[cur][kk + 1][ty * 2]);
                bn = *reinterpret_cast<const float4*>(&Bs[cur][kk + 1][tx * 4]);
            }
            c[0][0] = fmaf(ac.x, bc.x, c[0][0]);
            c[0][1] = fmaf(ac.x, bc.y, c[0][1]);
            c[0][2] = fmaf(ac.x, bc.z, c[0][2]);
            c[0][3] = fmaf(ac.x, bc.w, c[0][3]);
            c[1][0] = fmaf(ac.y, bc.x, c[1][0]);
            c[1][1] = fmaf(ac.y, bc.y, c[1][1]);
            c[1][2] = fmaf(ac.y, bc.z, c[1][2]);
            c[1][3] = fmaf(ac.y, bc.w, c[1][3]);
            if (kk < 31) { ac = an; bc = bn; }
        }
        if (more) {
            const int nxt = cur ^ 1;
            As[nxt][a_k4    ][a_m] = a0.x; As[nxt][a_k4 + 1][a_m] = a0.y;
            As[nxt][a_k4 + 2][a_m] = a0.z; As[nxt][a_k4 + 3][a_m] = a0.w;
            As[nxt][a_k4 + 16][a_m] = a1.x; As[nxt][a_k4 + 17][a_m] = a1.y;
            As[nxt][a_k4 + 18][a_m] = a1.z; As[nxt][a_k4 + 19][a_m] = a1.w;
            *reinterpret_cast<float4*>(&Bs[nxt][b_k][b_c4])      = bb0;
            *reinterpret_cast<float4*>(&Bs[nxt][b_k][b_c4 + 16]) = bb1;
            __syncthreads();
        }
    }
#pragma unroll
    for (int i = 0; i < 2; i++) {
        int m = m0 + ty * 2 + i;
#pragma unroll
        for (int j = 0; j < 4; j++) {
            int n = n0 + tx * 4 + j;
            float v = __fadd_rn(c[i][j], bias[n]);
            if (RELU) v = fmaxf(v, 0.0f);
            C[m * N + n] = v;
        }
    }
}

// ---------------- final layer: y = h3 @ Wout + bout  (512x512 @ 512x64) ----
// Same contract: single sequential ascending-k FFMA chain per element.
__global__ void gemm_out_kernel(const float* __restrict__ A,
                                const float* __restrict__ W,
                                const float* __restrict__ bias,
                                float* __restrict__ Y) {
    __shared__ float a[4][512];
    const int r0 = blockIdx.x * 4;
    const int t  = threadIdx.x;  // 64
    for (int idx = t; idx < 4 * 512; idx += 64)
        a[idx >> 9][idx & 511] = A[(r0 + (idx >> 9)) * 512 + (idx & 511)];
    __syncthreads();
    float acc[4] = {};
#pragma unroll 16
    for (int k = 0; k < 512; k++) {
        float w = W[k * 64 + t];         // coalesced; Wout stays in L2
#pragma unroll
        for (int r = 0; r < 4; r++) acc[r] = fmaf(a[r][k], w, acc[r]);
    }
    float b = bias[t];
#pragma unroll
    for (int r = 0; r < 4; r++) Y[(r0 + r) * 64 + t] = __fadd_rn(acc[r], b);
}

// ---------------- column means of y (4-partial fixed-order tree) ------------
__global__ void col_mean_kernel(const float* __restrict__ y) {
    __shared__ float ps[4][64];
    const int t = threadIdx.x;    // 256
    const int c = t & 63, p = t >> 6;
    float s = 0.0f;
    for (int r = p * 128; r < (p + 1) * 128; r++) s += y[r * 64 + c];
    ps[p][c] = s;
    __syncthreads();
    if (t < 64) {
        float v = __fadd_rn(__fadd_rn(__fadd_rn(ps[0][t], ps[1][t]), ps[2][t]), ps[3][t]);
        g_mean[t] = v * (1.0f / 512.0f);
    }
}

// ---------------- target MSE (as SSE) + compactness sum --------------------
__global__ void reduce_tc_kernel(const float* __restrict__ y,
                                 const float* __restrict__ target) {
    __shared__ double st[256];
    __shared__ double sc[256];
    const int tid = threadIdx.x;
    double t_sum = 0.0, c_sum = 0.0;
    for (int idx = blockIdx.x * 256 + tid; idx < 512 * 64; idx += gridDim.x * 256) {
        float yv = y[idx];
        float d  = target[idx] - yv;
        t_sum += (double)d * (double)d;
        c_sum += fabs((double)(yv - g_mean[idx & 63]));
    }
    st[tid] = t_sum; sc[tid] = c_sum;
    __syncthreads();
    for (int s = 128; s > 0; s >>= 1) {
        if (tid < s) { st[tid] += st[tid + s]; sc[tid] += sc[tid + s]; }
        __syncthreads();
    }
    if (tid == 0) {
        atomicAdd(&g_acc[0], st[0]);
        atomicAdd(&g_acc[2], sc[0]);
    }
}

// ---------------- sort deaths + reset accumulators --------------------------
__global__ void sort_deaths_kernel(const float* __restrict__ d, int n) {
    __shared__ float s[512];
    const int t = threadIdx.x;  // 512
    if (t < 3) g_acc[t] = 0.0;  // graph replays must be idempotent
    s[t] = (t < n) ? d[t] : 1e30f;
    __syncthreads();
    for (int k = 2; k <= 512; k <<= 1) {
        for (int j = k >> 1; j > 0; j >>= 1) {
            int ixj = t ^ j;
            if (ixj > t) {
                bool up = ((t & k) == 0);
                float a = s[t], b = s[ixj];
                if ((a > b) == up) { s[t] = b; s[ixj] = a; }
            }
            __syncthreads();
        }
    }
    g_deaths[t] = s[t];
}

// ---------------- pdist + tolerance match + homology sum --------------------
// BIT-EXACTNESS CONTRACT (IDENTIFIED Round 9, order 12):
//   16 leaves, leaf_q sequential: ((d_q^2 + d_{q+16}^2) + d_{q+32}^2) + d_{q+48}^2
//   then stride tree offsets 8,4,2,1 (fl adds), pd = fp32 sqrt.
// All via __fadd_rn/__fmul_rn so ptxas cannot contract to FMA.
// isclose in fp32 exactly as jax: |a-b| <= 1e-8f + 1e-6f*|b|.
__device__ __forceinline__ double pdist_row(const float* __restrict__ yi,
                                            const float* __restrict__ y,
                                            const float* __restrict__ ds,
                                            int i, int t, int n_deaths) {
    double local = 0.0;
    const float4* a4 = reinterpret_cast<const float4*>(yi);
    for (int j = i + 1 + t; j < 512; j += 128) {
        const float4* b4 = reinterpret_cast<const float4*>(y + j * 64);
        float d[64];
#pragma unroll
        for (int k = 0; k < 16; k++) {
            float4 a = a4[k], b = b4[k];
            d[4 * k]     = __fadd_rn(a.x, -b.x);
            d[4 * k + 1] = __fadd_rn(a.y, -b.y);
            d[4 * k + 2] = __fadd_rn(a.z, -b.z);
            d[4 * k + 3] = __fadd_rn(a.w, -b.w);
        }
        float l[16];
#pragma unroll
        for (int q = 0; q < 16; q++) {
            float s0 = __fmul_rn(d[q], d[q]);
            s0 = __fadd_rn(s0, __fmul_rn(d[q + 16], d[q + 16]));
            s0 = __fadd_rn(s0, __fmul_rn(d[q + 32], d[q + 32]));
            l[q] = __fadd_rn(s0, __fmul_rn(d[q + 48], d[q + 48]));
        }
#pragma unroll
        for (int off = 8; off > 0; off >>= 1)
#pragma unroll
            for (int q = 0; q < 8; q++)
                if (q < off) l[q] = __fadd_rn(l[q], l[q + off]);
        float pd = __fsqrt_rn(l[0]);

        int lo = 0, hi = 512;
        while (lo < hi) {
            int mid = (lo + hi) >> 1;
            if (ds[mid] < pd) lo = mid + 1; else hi = mid;
        }
        bool matched = false;
        int q0 = lo - 3 < 0 ? 0 : lo - 3;
        int q1 = lo + 2 < n_deaths - 1 ? lo + 2 : n_deaths - 1;
        for (int q = q0; q <= q1; q++) {
            float dd = ds[q];
            float rhs = __fadd_rn(1e-8f, __fmul_rn(1e-6f, fabsf(dd)));
            if (fabsf(__fadd_rn(pd, -dd)) <= rhs) matched = true;
        }
        if (matched) local += (double)pd;  // birth=0, EPS=0, pd>0
    }
    return local;
}

// Balanced: block b handles rows {b, 510-b} -> 512 pairs per block (const).
__global__ void pdist_hom_kernel(const float* __restrict__ y, int n_deaths) {
    __shared__ __align__(16) float yi[2][64];
    __shared__ float ds[512];
    __shared__ double red[128];
    const int b = blockIdx.x;   // 256 blocks
    const int t = threadIdx.x;  // 128
    const int i1 = b, i2 = 510 - b;
    if (t < 64) yi[0][t] = y[i1 * 64 + t];
    else if (i2 > i1) yi[1][t - 64] = y[i2 * 64 + (t - 64)];
    for (int k = t; k < 512; k += 128) ds[k] = g_deaths[k];
    __syncthreads();

    double local = pdist_row(yi[0], y, ds, i1, t, n_deaths);
    if (i2 > i1) local += pdist_row(yi[1], y, ds, i2, t, n_deaths);

    red[t] = local;
    __syncthreads();
    for (int s2 = 64; s2 > 0; s2 >>= 1) {
        if (t < s2) red[t] += red[t + s2];
        __syncthreads();
    }
    if (t == 0) atomicAdd(&g_acc[1], red[0]);
}

// ---------------- finalize ---------------------------------------------------
__global__ void finalize_kernel(float* __restrict__ out) {
    out[0] = (float)(g_acc[0] * (1.0 / 32768.0) + g_acc[1] + 0.01 * g_acc[2]);
}

// ---------------- launch -----------------------------------------------------
extern "C" void kernel_launch(void* const* d_in, const int* in_sizes, int n_in,
                              void* d_out, int out_size) {
    const float* batch  = (const float*)d_in[0];   // [512,256]
    const float* target = (const float*)d_in[1];   // [512,64]
    const float* W1     = (const float*)d_in[2];   // [256,512]
    const float* b1     = (const float*)d_in[3];
    const float* W2     = (const float*)d_in[4];   // [512,512]
    const float* b2     = (const float*)d_in[5];
    const float* W3     = (const float*)d_in[6];   // [512,512]
    const float* b3     = (const float*)d_in[7];
    const float* Wout   = (const float*)d_in[8];   // [512,64]
    const float* bout   = (const float*)d_in[9];
    const float* deaths = (const float*)d_in[10];  // [511]
    const int n_deaths  = in_sizes[10];
    float* out = (float*)d_out;

    void *p1, *p2, *p3, *py;
    cudaGetSymbolAddress(&p1, g_h1);
    cudaGetSymbolAddress(&p2, g_h2);
    cudaGetSymbolAddress(&p3, g_h3);
    cudaGetSymbolAddress(&py, g_y);
    float* h1 = (float*)p1; float* h2 = (float*)p2;
    float* h3 = (float*)p3; float* y  = (float*)py;

    sort_deaths_kernel<<<1, 512>>>(deaths, n_deaths);
    gemm32_kernel<true><<<dim3(16, 16), 128>>>(batch, W1, b1, h1, 256, 512);
    gemm32_kernel<true><<<dim3(16, 16), 128>>>(h1,    W2, b2, h2, 512, 512);
    gemm32_kernel<true><<<dim3(16, 16), 128>>>(h2,    W3, b3, h3, 512, 512);
    gemm_out_kernel<<<128, 64>>>(h3, Wout, bout, y);
    col_mean_kernel<<<1, 256>>>(y);
    reduce_tc_kernel<<<64, 256>>>(y, target);
    pdist_hom_kernel<<<256, 128>>>(y, n_deaths);
    finalize_kernel<<<1, 1>>>(out);
}